// round 17
// baseline (speedup 1.0000x reference)
#include <cuda_runtime.h>
#include <cuda_bf16.h>

// BPMLL loss — single graph node, packed-atomic tail, 1-MUFU element math
// with even/odd poly split (y-load off the math critical path).
//   Identity: sigmoid(x) = 1/2 + tanh(x/2)/2  =>  exp(sigmoid(x)) =
//   e^{1/2} exp(tanh(x/2)/2); all e^{+-1/2} and the e^{-1} bias cancel in
//   pos*neg*e^{-1}. tanh is odd, so compute t = tanh(c/2) from c ALONE, then
//   exp(+-t/2) = E(t^2) +- O(t^2)*t  (degree-4 Chebyshev split, err ~4e-5);
//   y is consumed only by the final select/add + ballots.
//   256 blocks x 256 threads; 128 threads/row (2 rows/block), 4 elems/thread.
//   Row reduce: ballot+popc counts (smem-stored before the butterflies) +
//   two interleaved shfl_xor butterflies. Leader: back-to-back rcp.approx,
//   then ONE atom.add.u64 packing {count: bits>=52, fixed sum(2^44): bits<52};
//   the block whose returned count == NBLK-1 holds the total in old+add,
//   writes out[0], resets g_pack for graph replay. Bit-deterministic sum.

#define ROWS 512
#define COLS 512
#define NBLK 256
#define TPB  256

// exp(t/2) on t in [-1,1], degree-4 (t-basis), split even/odd:
//   E(u) = P0 + P2 u + P4 u^2,  O(u) = P1 + P3 u,  u = t^2
//   exp(t/2) ~= E + t*O ;  exp(-t/2) ~= E - t*O
#define P0c 1.0f
#define P1c 0.49991862f
#define P2c 0.125f
#define P3c 0.021158854f
#define P4c 0.0026041667f

#define INV_ROWS (1.0f / 512.0f)

#define CNT_ONE   (1ULL << 52)
#define SUM_MASK  ((1ULL << 52) - 1ULL)
#define FIX_SCALE 0x1p44f
#define FIX_INV   0x1p-44f

__device__ unsigned long long g_pack = 0ULL;

// Math depends only on c; y selects the sign of the odd part at the end.
//   y==1 row term needs exp(sigmoid(-c))-normalized = E - t*O
//   y==0 row term needs exp(sigmoid(+c))-normalized = E + t*O
__device__ __forceinline__ void elem(float c, int y, float& pos, float& neg) {
    float t;
    asm("tanh.approx.f32 %0, %1;" : "=f"(t) : "f"(c * 0.5f));   // 1 MUFU, c-only
    float u  = t * t;
    float E  = fmaf(fmaf(P4c, u, P2c), u, P0c);
    float Ot = t * fmaf(P3c, u, P1c);
    if (y) pos += (E - Ot); else neg += (E + Ot);
}

__global__ __launch_bounds__(TPB) void bpmll_kernel(const float* __restrict__ c,
                                                    const int*   __restrict__ y,
                                                    float* __restrict__ out) {
    const int tid    = threadIdx.x;
    const int lane   = tid & 31;
    const int warp   = tid >> 5;          // 0..7
    const int tid128 = tid & 127;
    const int row    = blockIdx.x * 2 + (tid >> 7);

    const float4 cv = reinterpret_cast<const float4*>(c)[(size_t)row * (COLS / 4) + tid128];
    const int4   yv = reinterpret_cast<const int4*>(y)[(size_t)row * (COLS / 4) + tid128];

    float pos = 0.0f, neg = 0.0f;
    elem(cv.x, yv.x, pos, neg);
    elem(cv.y, yv.y, pos, neg);
    elem(cv.z, yv.z, pos, neg);
    elem(cv.w, yv.w, pos, neg);

    __shared__ float sp[8];
    __shared__ float sn[8];
    __shared__ int   si[8];

    // Counts (independent of the float math) — store to smem early.
    int ys = __popc(__ballot_sync(0xFFFFFFFFu, yv.x))
           + __popc(__ballot_sync(0xFFFFFFFFu, yv.y))
           + __popc(__ballot_sync(0xFFFFFFFFu, yv.z))
           + __popc(__ballot_sync(0xFFFFFFFFu, yv.w));
    if (lane == 0) si[warp] = ys;

    // Two interleaved butterfly chains — latency overlaps.
    #pragma unroll
    for (int o = 16; o > 0; o >>= 1) {
        pos += __shfl_xor_sync(0xFFFFFFFFu, pos, o);
        neg += __shfl_xor_sync(0xFFFFFFFFu, neg, o);
    }
    if (lane == 0) { sp[warp] = pos; sn[warp] = neg; }
    __syncthreads();

    if (tid == 0) {
        // Row 0 = warps 0-3, row 1 = warps 4-7.
        int   Y0  = (si[0] + si[1]) + (si[2] + si[3]);
        int   Y1  = (si[4] + si[5]) + (si[6] + si[7]);
        float D0f = (float)Y0 * (float)(COLS - Y0);
        float D1f = (float)Y1 * (float)(COLS - Y1);
        float R0, R1;
        asm("rcp.approx.f32 %0, %1;" : "=f"(R0) : "f"(D0f));
        asm("rcp.approx.f32 %0, %1;" : "=f"(R1) : "f"(D1f));

        float P0s = (sp[0] + sp[1]) + (sp[2] + sp[3]);
        float N0s = (sn[0] + sn[1]) + (sn[2] + sn[3]);
        float P1s = (sp[4] + sp[5]) + (sp[6] + sp[7]);
        float N1s = (sn[4] + sn[5]) + (sn[6] + sn[7]);

        float part = fmaf(P0s * N0s * INV_ROWS, R0,
                          P1s * N1s * INV_ROWS * R1);

        // Packed count+sum atomic: one L2 round trip finishes everything.
        unsigned long long add = CNT_ONE + __float2ull_rn(part * FIX_SCALE);
        unsigned long long old;
        asm volatile("atom.global.add.u64 %0, [%1], %2;"
                     : "=l"(old) : "l"(&g_pack), "l"(add) : "memory");

        if ((old >> 52) == (unsigned long long)(NBLK - 1)) {
            unsigned long long total_fix = (old + add) & SUM_MASK;
            out[0] = (float)((double)total_fix) * FIX_INV;
            asm volatile("st.global.cg.u64 [%0], %1;"
                         :: "l"(&g_pack), "l"(0ULL) : "memory");
        }
    }
}

extern "C" void kernel_launch(void* const* d_in, const int* in_sizes, int n_in,
                              void* d_out, int out_size) {
    const float* c = (const float*)d_in[0];
    const int*   y = (const int*)d_in[1];
    float*       out = (float*)d_out;
    bpmll_kernel<<<NBLK, TPB>>>(c, y, out);
}